// round 4
// baseline (speedup 1.0000x reference)
#include <cuda_runtime.h>
#include <cuda_bf16.h>

typedef unsigned int  u32;
typedef unsigned short u16;

// ---------------- scratch (device globals; allocation-free) ----------------
__device__ float g_hA[16384*256];
__device__ float g_hB[16384*256];
__device__ float g_c [16384*256];
__device__ float g_childA[16384*256];
__device__ float g_childB[4096*256];
__device__ float g_xw[16384*1024];      // x@W_ih^T + biases, layout [m][jj*4+g]
__device__ float g_WcatT[512*1024];     // [k][jj*4+g]  (k<256: W_ih, else W_hh)
__device__ float g_Wcomb[256*512];      // Wt @ Wc, row-major [i][k]
__device__ float g_WcombHT[256*256];    // transposed h-half: [k][i]
__device__ float g_bcomb[256];
__device__ float g_tagE[26*256];
__device__ float g_leafout[26*256];
__device__ float g_leafxW[26*1024];     // [v][jj*4+g], biases folded in
__device__ float g_h1[256];
__device__ float g_c1[256];
__device__ float g_bzT[1024];
__device__ float g_hh1[1024];           // W_hh^T-proj of h1, layout [jj*4+g]
__device__ float g_h676[676*256];
__device__ float g_c676[676*256];

// bf16 planes
__device__ u16 g_hbfA_hi[16384*256], g_hbfA_lo[16384*256];
__device__ u16 g_hbfB_hi[16384*256], g_hbfB_lo[16384*256];
__device__ u16 g_chbf_hi[16384*256],  g_chbf_lo[16384*256];
__device__ u16 g_h676bf_hi[676*256],  g_h676bf_lo[676*256];
__device__ u16 g_h1bf_hi[256],        g_h1bf_lo[256];
// prepacked B fragments: [kt(16)][nw(32)][lane(32)][nt(4)][reg(2)]
__device__ u32 g_BPhh_hi[131072], g_BPhh_lo[131072];
__device__ u32 g_BPih_hi[131072], g_BPih_lo[131072];

__device__ __forceinline__ float sigm(float x){ return 1.0f/(1.0f+expf(-x)); }

__device__ __forceinline__ u16 bfhi(float x){
    __nv_bfloat16 b = __float2bfloat16(x);
    return *reinterpret_cast<u16*>(&b);
}
__device__ __forceinline__ float bf2f(u16 u){
    __nv_bfloat16 b = *reinterpret_cast<__nv_bfloat16*>(&u);
    return __bfloat162float(b);
}
__device__ __forceinline__ void bfsplit(float x, u16& hi, u16& lo){
    hi = bfhi(x);
    lo = bfhi(x - bf2f(hi));
}

__device__ __forceinline__ void mma_bf16(float* c, u32 a0,u32 a1,u32 a2,u32 a3, u32 b0,u32 b1){
    asm volatile("mma.sync.aligned.m16n8k16.row.col.f32.bf16.bf16.f32 "
        "{%0,%1,%2,%3}, {%4,%5,%6,%7}, {%8,%9}, {%0,%1,%2,%3};"
        : "+f"(c[0]),"+f"(c[1]),"+f"(c[2]),"+f"(c[3])
        : "r"(a0),"r"(a1),"r"(a2),"r"(a3),"r"(b0),"r"(b1));
}

// ---------------- fused prologue kernels ----------------
// pre1: blocks 0..511 -> Wcomb, block 512 -> bcomb
__global__ void k_pre1(const float* __restrict__ Wt, const float* __restrict__ Wc,
                       const float* __restrict__ bc, const float* __restrict__ bt)
{
    int blk = blockIdx.x, tid = threadIdx.x;
    if (blk < 512){
        int idx = blk*256 + tid;
        int i = idx >> 9, k = idx & 511;
        float s = 0.f;
        #pragma unroll 8
        for (int j = 0; j < 256; j++) s += Wt[i*256+j]*Wc[j*512+k];
        g_Wcomb[idx] = s;
    } else {
        float s = bt[tid];
        #pragma unroll 8
        for (int j = 0; j < 256; j++) s += Wt[tid*256+j]*bc[j];
        g_bcomb[tid] = s;
    }
}

// pre2: [0..255] wcombHT, [256..281] tagE, [282..2329] wcatT, [2330] bzT, [2331] init_h1c1
__global__ void k_pre2(const float* __restrict__ W_ih, const float* __restrict__ W_hh,
                       const float* __restrict__ b_ih, const float* __restrict__ b_hh,
                       const float* __restrict__ emb, const float* __restrict__ lstm_init)
{
    int blk = blockIdx.x, tid = threadIdx.x;
    if (blk < 256){
        int idx = blk*256 + tid;
        int k = idx >> 8, i = idx & 255;
        g_WcombHT[idx] = g_Wcomb[i*512 + k];
    } else if (blk < 282){
        int v = blk - 256, i = tid;
        __shared__ float es[256];
        es[i] = emb[v*256 + i];
        __syncthreads();
        float s = 0.f;
        #pragma unroll 8
        for (int k = 0; k < 256; k++) s += es[k]*g_Wcomb[i*512 + 256 + k];
        g_tagE[v*256 + i] = s;
    } else if (blk < 2330){
        int idx = (blk-282)*256 + tid;
        int k = idx >> 10, col = idx & 1023;
        int jj = col >> 2, g = col & 3;
        int row = g*256 + jj;
        g_WcatT[idx] = (k < 256) ? W_ih[row*256 + k] : W_hh[row*256 + (k-256)];
    } else if (blk == 2330){
        #pragma unroll
        for (int r = 0; r < 4; r++){
            int idx = tid + r*256;
            int jj = idx >> 2, g = idx & 3;
            g_bzT[idx] = b_ih[g*256+jj] + b_hh[g*256+jj];
        }
    } else {
        __shared__ float xs[256], z[1024];
        xs[tid] = lstm_init[tid];
        __syncthreads();
        #pragma unroll
        for (int r = 0; r < 4; r++){
            int j = tid + r*256;
            float s = b_ih[j] + b_hh[j];
            const float* w = &W_ih[j*256];
            #pragma unroll 8
            for (int k = 0; k < 256; k++) s += xs[k]*w[k];
            z[j] = s;
        }
        __syncthreads();
        float c = sigm(z[tid]) * tanhf(z[tid+512]);
        g_c1[tid] = c;
        g_h1[tid] = sigm(z[tid+768]) * tanhf(c);
    }
}

__device__ void prepack_one(const float* __restrict__ WT, u32* BH, u32* BL, int idx)
{
    int r = idx & 1, nt = (idx>>1)&3, lane = (idx>>3)&31, nw = (idx>>8)&31, kt = idx>>13;
    int n = nw*32 + nt*8 + (lane>>2);
    int k = kt*16 + (lane&3)*2 + r*8;
    u16 h0,l0,h1,l1;
    bfsplit(WT[k*1024 + n], h0, l0);
    bfsplit(WT[(k+1)*1024 + n], h1, l1);
    BH[idx] = (u32)h0 | ((u32)h1<<16);
    BL[idx] = (u32)l0 | ((u32)l1<<16);
}

// pre3: [0..25] leafout, [26..29] hh1, [30..541] prepack hh, [542..1053] prepack ih, [1054] h1bf
__global__ void k_pre3()
{
    int blk = blockIdx.x, tid = threadIdx.x;
    if (blk < 26){
        int v = blk, i = tid;
        __shared__ float h1s[256];
        __shared__ float red[256];
        h1s[i] = g_h1[i];
        __syncthreads();
        float s = g_tagE[v*256+i] + g_bcomb[i];
        #pragma unroll 8
        for (int k = 0; k < 256; k++) s += h1s[k]*g_Wcomb[i*512 + k];
        red[i] = s; __syncthreads();
        for (int st = 128; st > 0; st >>= 1){ if (i < st) red[i] = fmaxf(red[i], red[i+st]); __syncthreads(); }
        float mx = red[0]; __syncthreads();
        red[i] = expf(s - mx); __syncthreads();
        for (int st = 128; st > 0; st >>= 1){ if (i < st) red[i] += red[i+st]; __syncthreads(); }
        float lse = mx + logf(red[0]);
        g_leafout[v*256 + i] = s - lse;
    } else if (blk < 30){
        __shared__ float h1s[256];
        int col = (blk-26)*256 + tid;
        h1s[tid] = g_h1[tid];
        __syncthreads();
        const float* w = g_WcatT + 256*1024;
        float s = 0.f;
        #pragma unroll 8
        for (int k = 0; k < 256; k++) s += h1s[k]*w[k*1024 + col];
        g_hh1[col] = s;
    } else if (blk < 542){
        prepack_one(g_WcatT + 256*1024, g_BPhh_hi, g_BPhh_lo, (blk-30)*256 + tid);
    } else if (blk < 1054){
        prepack_one(g_WcatT, g_BPih_hi, g_BPih_lo, (blk-542)*256 + tid);
    } else {
        bfsplit(g_h1[tid], g_h1bf_hi[tid], g_h1bf_lo[tid]);
    }
}

__global__ void k_leafxw(const float* __restrict__ W_ih, const float* __restrict__ b_ih,
                         const float* __restrict__ b_hh)
{
    int blk = blockIdx.x;           // 0..103 = v*4 + jb
    int v = blk >> 2, jb = blk & 3;
    int c = jb*256 + threadIdx.x;
    int jj = c >> 2, g = c & 3;
    int row = g*256 + jj;
    __shared__ float lo[256];
    lo[threadIdx.x] = g_leafout[v*256 + threadIdx.x];
    __syncthreads();
    float s = b_ih[row] + b_hh[row];
    #pragma unroll 8
    for (int k = 0; k < 256; k++) s += lo[k]*W_ih[row*256 + k];
    g_leafxW[v*1024 + c] = s;
}

// ---------------- SIMT small GEMM (levels with M < 1024) ----------------
// MODE 0: xw = x @ W_ih^T + bzT
// MODE 1: LSTM step, add = xw[(gm*4+t)]
// MODE 3: 676 pair states; A row = h26[gm/26] computed inline from hh1+leafxW; add = leafxW[gm%26]
template<int MODE>
__global__ void __launch_bounds__(256)
gemm_small(const float* __restrict__ hin, float* __restrict__ hout,
           const float* __restrict__ cin, float* __restrict__ cout,
           const float* __restrict__ WT,
           const int* __restrict__ ids,
           const float* __restrict__ addbase,
           const float* __restrict__ c1v,
           int first, int M,
           u16* __restrict__ bh, u16* __restrict__ bl)
{
    __shared__ float hs[16*264];
    __shared__ int rmap[16], aidx[16];
    int tid = threadIdx.x;
    int r = tid >> 4, tj = tid & 15;
    int m0 = blockIdx.x * 16;
    int j0q = blockIdx.y * 32;

    if (tid < 16){
        int gm = m0 + tid;
        int rr = 0, a = 0;
        if (gm < M){
            if (MODE == 0){ rr = gm; }
            else if (MODE == 1){ rr = gm; a = gm*4; }
            else { rr = gm/26; a = gm - rr*26; }
        }
        rmap[tid] = rr; aidx[tid] = a;
    }
    __syncthreads();
    if (MODE == 3){
        #pragma unroll
        for (int q = 0; q < 16; q++){
            int e = tid + q*256;
            int row = e >> 8, k = e & 255;
            int i0 = rmap[row];
            float4 zh = *reinterpret_cast<const float4*>(&g_hh1[k*4]);
            float4 zl = *reinterpret_cast<const float4*>(&addbase[i0*1024 + k*4]);
            float cz = sigm(zh.y+zl.y)*c1v[k] + sigm(zh.x+zl.x)*tanhf(zh.z+zl.z);
            hs[row*264 + k] = sigm(zh.w+zl.w)*tanhf(cz);
        }
    } else {
        #pragma unroll
        for (int q = 0; q < 4; q++){
            int e = tid + q*256;
            int row = e >> 6, c4 = e & 63;
            int gm = m0 + row;
            float4 v = make_float4(0.f,0.f,0.f,0.f);
            if (gm < M)
                v = (MODE != 0 && first) ? *reinterpret_cast<const float4*>(&hin[c4*4])
                                         : *reinterpret_cast<const float4*>(&hin[rmap[row]*256 + c4*4]);
            *reinterpret_cast<float4*>(&hs[row*264 + c4*4]) = v;
        }
    }
    __syncthreads();

    int q0 = j0q + tj, q1 = j0q + tj + 16;
    float4 acc0 = make_float4(0.f,0.f,0.f,0.f);
    float4 acc1 = make_float4(0.f,0.f,0.f,0.f);
    const float* w0 = WT + q0*4;
    const float* w1 = WT + q1*4;
    #pragma unroll 4
    for (int k = 0; k < 256; k++){
        float a = hs[r*264 + k];
        float4 b0 = *reinterpret_cast<const float4*>(&w0[k*1024]);
        float4 b1 = *reinterpret_cast<const float4*>(&w1[k*1024]);
        acc0.x = fmaf(a,b0.x,acc0.x); acc0.y = fmaf(a,b0.y,acc0.y);
        acc0.z = fmaf(a,b0.z,acc0.z); acc0.w = fmaf(a,b0.w,acc0.w);
        acc1.x = fmaf(a,b1.x,acc1.x); acc1.y = fmaf(a,b1.y,acc1.y);
        acc1.z = fmaf(a,b1.z,acc1.z); acc1.w = fmaf(a,b1.w,acc1.w);
    }
    int gm = m0 + r;
    if (gm >= M) return;
    if (MODE == 0){
        float4 bz0 = *reinterpret_cast<const float4*>(&addbase[q0*4]);
        float4 bz1 = *reinterpret_cast<const float4*>(&addbase[q1*4]);
        *reinterpret_cast<float4*>(&hout[gm*1024 + q0*4]) =
            make_float4(acc0.x+bz0.x, acc0.y+bz0.y, acc0.z+bz0.z, acc0.w+bz0.w);
        *reinterpret_cast<float4*>(&hout[gm*1024 + q1*4]) =
            make_float4(acc1.x+bz1.x, acc1.y+bz1.y, acc1.z+bz1.z, acc1.w+bz1.w);
    } else {
        const float* ad = addbase + aidx[r]*1024;
        float4 a0 = *reinterpret_cast<const float4*>(&ad[q0*4]);
        float4 a1 = *reinterpret_cast<const float4*>(&ad[q1*4]);
        float cold0, cold1;
        if (MODE == 3){
            float4 zh0 = *reinterpret_cast<const float4*>(&g_hh1[q0*4]);
            float4 zl0 = *reinterpret_cast<const float4*>(&addbase[rmap[r]*1024 + q0*4]);
            cold0 = sigm(zh0.y+zl0.y)*c1v[q0] + sigm(zh0.x+zl0.x)*tanhf(zh0.z+zl0.z);
            float4 zh1 = *reinterpret_cast<const float4*>(&g_hh1[q1*4]);
            float4 zl1 = *reinterpret_cast<const float4*>(&addbase[rmap[r]*1024 + q1*4]);
            cold1 = sigm(zh1.y+zl1.y)*c1v[q1] + sigm(zh1.x+zl1.x)*tanhf(zh1.z+zl1.z);
        } else {
            cold0 = first ? c1v[q0] : cin[rmap[r]*256 + q0];
            cold1 = first ? c1v[q1] : cin[rmap[r]*256 + q1];
        }
        {
            float zi = acc0.x+a0.x, zf = acc0.y+a0.y, zg = acc0.z+a0.z, zo = acc0.w+a0.w;
            float cn = sigm(zf)*cold0 + sigm(zi)*tanhf(zg);
            cout[gm*256 + q0] = cn;
            float hn = sigm(zo)*tanhf(cn);
            hout[gm*256 + q0] = hn;
            if (MODE == 3){ bfsplit(hn, bh[gm*256+q0], bl[gm*256+q0]); }
        }
        {
            float zi = acc1.x+a1.x, zf = acc1.y+a1.y, zg = acc1.z+a1.z, zo = acc1.w+a1.w;
            float cn = sigm(zf)*cold1 + sigm(zi)*tanhf(zg);
            cout[gm*256 + q1] = cn;
            float hn = sigm(zo)*tanhf(cn);
            hout[gm*256 + q1] = hn;
            if (MODE == 3){ bfsplit(hn, bh[gm*256+q1], bl[gm*256+q1]); }
        }
    }
}

// ---------------- MMA GEMM (M multiple of 64, >= 1024) ----------------
// MODE 0: xw (fp32 out, stride 1024); MODE 1: step w/ xw add; MODE 2: step leafxW[ids];
// MODE 4: step triples, A row = id0*26+id1, add = leafxW[id2]
template<int MODE>
__global__ void __launch_bounds__(256)
mma_step(const u16* __restrict__ hin_hi, const u16* __restrict__ hin_lo,
         float* __restrict__ hout, u16* __restrict__ hbf_hi, u16* __restrict__ hbf_lo,
         const float* __restrict__ cin, float* __restrict__ cout,
         const u32* __restrict__ BP_hi, const u32* __restrict__ BP_lo,
         const int* __restrict__ ids,
         const float* __restrict__ addbase,
         const float* __restrict__ c1v,
         int first, int M)
{
    __shared__ u16 As_hi[64*40];
    __shared__ u16 As_lo[64*40];
    __shared__ int rmap[64], aidx[64];

    int tid = threadIdx.x;
    int warp = tid >> 5, lane = tid & 31;
    int wr = warp >> 2, wc = warp & 3;
    int m0 = blockIdx.x * 64;
    int j0 = blockIdx.y * 128;

    if (tid < 64){
        int gm = m0 + tid;
        int r = 0, a = 0;
        if (MODE == 0){ r = gm; }
        else if (MODE == 1){ r = gm; a = gm*4; }
        else if (MODE == 2){ r = gm; a = ids[gm*4]; }
        else { int i0 = ids[gm*4], i1 = ids[gm*4+1]; a = ids[gm*4+2]; r = i0*26 + i1; }
        rmap[tid] = r; aidx[tid] = a;
    }
    __syncthreads();

    float c[2][4][4];
    #pragma unroll
    for (int a = 0; a < 2; a++)
        #pragma unroll
        for (int b = 0; b < 4; b++)
            #pragma unroll
            for (int d = 0; d < 4; d++) c[a][b][d] = 0.f;

    int arow = tid >> 2, aseg = tid & 3;
    int srcrow = first ? 0 : rmap[arow];
    int nwg = blockIdx.y*4 + wc;

    for (int k0 = 0; k0 < 256; k0 += 32){
        *reinterpret_cast<uint4*>(&As_hi[arow*40 + aseg*8]) =
            *reinterpret_cast<const uint4*>(&hin_hi[srcrow*256 + k0 + aseg*8]);
        *reinterpret_cast<uint4*>(&As_lo[arow*40 + aseg*8]) =
            *reinterpret_cast<const uint4*>(&hin_lo[srcrow*256 + k0 + aseg*8]);
        __syncthreads();
        #pragma unroll
        for (int kt = 0; kt < 2; kt++){
            int ktg = (k0 >> 4) + kt;
            const u32* bph = BP_hi + (((ktg*32 + nwg)*32 + lane)<<3);
            const u32* bpl = BP_lo + (((ktg*32 + nwg)*32 + lane)<<3);
            uint4 bh0 = *reinterpret_cast<const uint4*>(bph);
            uint4 bh1 = *reinterpret_cast<const uint4*>(bph+4);
            uint4 bl0 = *reinterpret_cast<const uint4*>(bpl);
            uint4 bl1 = *reinterpret_cast<const uint4*>(bpl+4);
            #pragma unroll
            for (int mt = 0; mt < 2; mt++){
                int ab = (wr*32 + mt*16 + (lane>>2))*40 + kt*16 + ((lane&3)<<1);
                u32 ah0 = *reinterpret_cast<const u32*>(&As_hi[ab]);
                u32 ah1 = *reinterpret_cast<const u32*>(&As_hi[ab+320]);
                u32 ah2 = *reinterpret_cast<const u32*>(&As_hi[ab+8]);
                u32 ah3 = *reinterpret_cast<const u32*>(&As_hi[ab+328]);
                u32 al0 = *reinterpret_cast<const u32*>(&As_lo[ab]);
                u32 al1 = *reinterpret_cast<const u32*>(&As_lo[ab+320]);
                u32 al2 = *reinterpret_cast<const u32*>(&As_lo[ab+8]);
                u32 al3 = *reinterpret_cast<const u32*>(&As_lo[ab+328]);
                mma_bf16(c[mt][0], ah0,ah1,ah2,ah3, bh0.x,bh0.y);
                mma_bf16(c[mt][0], ah0,ah1,ah2,ah3, bl0.x,bl0.y);
                mma_bf16(c[mt][0], al0,al1,al2,al3, bh0.x,bh0.y);
                mma_bf16(c[mt][1], ah0,ah1,ah2,ah3, bh0.z,bh0.w);
                mma_bf16(c[mt][1], ah0,ah1,ah2,ah3, bl0.z,bl0.w);
                mma_bf16(c[mt][1], al0,al1,al2,al3, bh0.z,bh0.w);
                mma_bf16(c[mt][2], ah0,ah1,ah2,ah3, bh1.x,bh1.y);
                mma_bf16(c[mt][2], ah0,ah1,ah2,ah3, bl1.x,bl1.y);
                mma_bf16(c[mt][2], al0,al1,al2,al3, bh1.x,bh1.y);
                mma_bf16(c[mt][3], ah0,ah1,ah2,ah3, bh1.z,bh1.w);
                mma_bf16(c[mt][3], ah0,ah1,ah2,ah3, bl1.z,bl1.w);
                mma_bf16(c[mt][3], al0,al1,al2,al3, bh1.z,bh1.w);
            }
        }
        __syncthreads();
    }

    if (MODE == 0){
        #pragma unroll
        for (int mt = 0; mt < 2; mt++)
            #pragma unroll
            for (int nt = 0; nt < 4; nt++){
                int row = m0 + wr*32 + mt*16 + (lane>>2);
                int col = j0 + wc*32 + nt*8 + ((lane&3)<<1);
                float2 bz = *reinterpret_cast<const float2*>(&addbase[col]);
                float2 v0 = make_float2(c[mt][nt][0]+bz.x, c[mt][nt][1]+bz.y);
                float2 v1 = make_float2(c[mt][nt][2]+bz.x, c[mt][nt][3]+bz.y);
                *reinterpret_cast<float2*>(&hout[row*1024 + col]) = v0;
                *reinterpret_cast<float2*>(&hout[(row+8)*1024 + col]) = v1;
            }
    } else {
        bool ev = !(lane & 1);
        #pragma unroll
        for (int mt = 0; mt < 2; mt++)
            #pragma unroll
            for (int nt = 0; nt < 4; nt++){
                float c0 = c[mt][nt][0], c1_ = c[mt][nt][1], c2 = c[mt][nt][2], c3 = c[mt][nt][3];
                float r0 = __shfl_xor_sync(0xffffffffu, c0, 1);
                float r1 = __shfl_xor_sync(0xffffffffu, c1_, 1);
                float r2 = __shfl_xor_sync(0xffffffffu, c2, 1);
                float r3 = __shfl_xor_sync(0xffffffffu, c3, 1);
                int rl = wr*32 + mt*16 + (lane>>2) + (ev ? 0 : 8);
                int gm = m0 + rl;
                int jj = ((j0 + wc*32 + nt*8) >> 2) + ((lane>>1)&1);
                float zi = ev ? c0 : r2;
                float zf = ev ? c1_ : r3;
                float zg = ev ? r0 : c2;
                float zo = ev ? r1 : c3;
                const float* ad = addbase + aidx[rl]*1024 + jj*4;
                float4 a4 = *reinterpret_cast<const float4*>(ad);
                zi += a4.x; zf += a4.y; zg += a4.z; zo += a4.w;
                float cold = first ? c1v[jj] : cin[rmap[rl]*256 + jj];
                float cn = sigm(zf)*cold + sigm(zi)*tanhf(zg);
                float hn = sigm(zo)*tanhf(cn);
                cout[gm*256 + jj] = cn;
                hout[gm*256 + jj] = hn;
                bfsplit(hn, hbf_hi[gm*256 + jj], hbf_lo[gm*256 + jj]);
            }
    }
}

// ---------------- tag + log_softmax ----------------
__global__ void tag_kernel(const float* __restrict__ h, const int* __restrict__ ids,
                           float* __restrict__ out, int M,
                           u16* __restrict__ bh, u16* __restrict__ bl)
{
    __shared__ float As[32][20];
    __shared__ float Ws[32][256];
    __shared__ float red[16][16];
    __shared__ float rowmax[16], rowlse[16];
    float* stag = &Ws[0][0];

    int tid = threadIdx.x;
    int rg = tid >> 6;
    int cg = tid & 63;
    int m0 = blockIdx.x * 16;

    float acc[4][4];
    #pragma unroll
    for (int a = 0; a < 4; a++)
        #pragma unroll
        for (int b = 0; b < 4; b++) acc[a][b] = 0.f;

    for (int k0 = 0; k0 < 256; k0 += 32){
        #pragma unroll
        for (int q = 0; q < 2; q++){
            int e = tid + q*256;
            int m = e >> 5, kk = e & 31;
            int gm = m0 + m;
            As[kk][m] = (gm < M) ? h[gm*256 + k0 + kk] : 0.f;
        }
        #pragma unroll
        for (int q = 0; q < 8; q++){
            int e = tid + q*256;
            int kk = e >> 6, c4 = e & 63;
            *reinterpret_cast<float4*>(&Ws[kk][c4*4]) =
                *reinterpret_cast<const float4*>(&g_WcombHT[(k0+kk)*256 + c4*4]);
        }
        __syncthreads();
        #pragma unroll
        for (int kk = 0; kk < 32; kk++){
            float4 a = *reinterpret_cast<const float4*>(&As[kk][rg*4]);
            float4 b = *reinterpret_cast<const float4*>(&Ws[kk][cg*4]);
            acc[0][0] = fmaf(a.x, b.x, acc[0][0]); acc[0][1] = fmaf(a.x, b.y, acc[0][1]);
            acc[0][2] = fmaf(a.x, b.z, acc[0][2]); acc[0][3] = fmaf(a.x, b.w, acc[0][3]);
            acc[1][0] = fmaf(a.y, b.x, acc[1][0]); acc[1][1] = fmaf(a.y, b.y, acc[1][1]);
            acc[1][2] = fmaf(a.y, b.z, acc[1][2]); acc[1][3] = fmaf(a.y, b.w, acc[1][3]);
            acc[2][0] = fmaf(a.z, b.x, acc[2][0]); acc[2][1] = fmaf(a.z, b.y, acc[2][1]);
            acc[2][2] = fmaf(a.z, b.z, acc[2][2]); acc[2][3] = fmaf(a.z, b.w, acc[2][3]);
            acc[3][0] = fmaf(a.w, b.x, acc[3][0]); acc[3][1] = fmaf(a.w, b.y, acc[3][1]);
            acc[3][2] = fmaf(a.w, b.z, acc[3][2]); acc[3][3] = fmaf(a.w, b.w, acc[3][3]);
        }
        __syncthreads();
    }

    float4 bc = *reinterpret_cast<const float4*>(&g_bcomb[cg*4]);
    #pragma unroll
    for (int ri = 0; ri < 4; ri++){
        int r = rg*4 + ri;
        int gm = m0 + r;
        int id = (gm < M) ? ids[gm] : 0;
        float4 te = *reinterpret_cast<const float4*>(&g_tagE[id*256 + cg*4]);
        float4 v = make_float4(acc[ri][0]+te.x+bc.x, acc[ri][1]+te.y+bc.y,
                               acc[ri][2]+te.z+bc.z, acc[ri][3]+te.w+bc.w);
        *reinterpret_cast<float4*>(&stag[r*256 + cg*4]) = v;
    }
    __syncthreads();
    {
        int r = tid >> 4, s = tid & 15;
        float mx = -1e30f;
        #pragma unroll
        for (int q = 0; q < 16; q++) mx = fmaxf(mx, stag[r*256 + s*16 + q]);
        red[r][s] = mx;
    }
    __syncthreads();
    if (tid < 16){
        float mx = red[tid][0];
        #pragma unroll
        for (int s = 1; s < 16; s++) mx = fmaxf(mx, red[tid][s]);
        rowmax[tid] = mx;
    }
    __syncthreads();
    {
        int r = tid >> 4, s = tid & 15;
        float sm = 0.f, mx = rowmax[r];
        #pragma unroll
        for (int q = 0; q < 16; q++) sm += expf(stag[r*256 + s*16 + q] - mx);
        red[r][s] = sm;
    }
    __syncthreads();
    if (tid < 16){
        float sm = 0.f;
        #pragma unroll
        for (int s = 0; s < 16; s++) sm += red[tid][s];
        rowlse[tid] = logf(sm);
    }
    __syncthreads();
    #pragma unroll
    for (int q = 0; q < 16; q++){
        int e = tid + q*256;
        int r = e >> 8, i = e & 255;
        int gm = m0 + r;
        if (gm < M){
            float v = stag[r*256 + i] - rowmax[r] - rowlse[r];
            out[gm*256 + i] = v;
            if (bh){ bfsplit(v, bh[gm*256+i], bl[gm*256+i]); }
        }
    }
}

// ---------------- host launcher ----------------
extern "C" void kernel_launch(void* const* d_in, const int* in_sizes, int n_in,
                              void* d_out, int out_size)
{
    const int*   idents    = (const int*)  d_in[0];
    const float* emb       = (const float*)d_in[1];
    const float* W_ih      = (const float*)d_in[2];
    const float* W_hh      = (const float*)d_in[3];
    const float* b_ih      = (const float*)d_in[4];
    const float* b_hh      = (const float*)d_in[5];
    const float* Wc        = (const float*)d_in[6];
    const float* bc        = (const float*)d_in[7];
    const float* Wt        = (const float*)d_in[8];
    const float* bt        = (const float*)d_in[9];
    const float* lstm_init = (const float*)d_in[10];
    float* out = (float*)d_out;
    (void)in_sizes; (void)n_in; (void)out_size;

    void* p;
    float *hA, *hB, *cbuf, *chA, *chB, *xw, *wcatT, *leafxW, *bzT, *h1, *c1;
    float *h676, *c676;
    u16 *bfAh, *bfAl, *bfBh, *bfBl, *chbh, *chbl, *b676h, *b676l, *h1bh, *h1bl;
    u32 *bphh_h, *bphh_l, *bpih_h, *bpih_l;
    cudaGetSymbolAddress(&p, g_hA);     hA     = (float*)p;
    cudaGetSymbolAddress(&p, g_hB);     hB     = (float*)p;
    cudaGetSymbolAddress(&p, g_c);      cbuf   = (float*)p;
    cudaGetSymbolAddress(&p, g_childA); chA    = (float*)p;
    cudaGetSymbolAddress(&p, g_childB); chB    = (float*)p;
    cudaGetSymbolAddress(&p, g_xw);     xw     = (float*)p;
    cudaGetSymbolAddress(&p, g_WcatT);  wcatT  = (float*)p;
    cudaGetSymbolAddress(&p, g_leafxW); leafxW = (float*)p;
    cudaGetSymbolAddress(&p, g_bzT);    bzT    = (float*)p;
    cudaGetSymbolAddress(&p, g_h1);     h1     = (float*)p;
    cudaGetSymbolAddress(&p, g_c1);     c1     = (float*)p;
    cudaGetSymbolAddress(&p, g_h676);   h676   = (float*)p;
    cudaGetSymbolAddress(&p, g_c676);   c676   = (float*)p;
    cudaGetSymbolAddress(&p, g_hbfA_hi); bfAh = (u16*)p;
    cudaGetSymbolAddress(&p, g_hbfA_lo); bfAl = (u16*)p;
    cudaGetSymbolAddress(&p, g_hbfB_hi); bfBh = (u16*)p;
    cudaGetSymbolAddress(&p, g_hbfB_lo); bfBl = (u16*)p;
    cudaGetSymbolAddress(&p, g_chbf_hi); chbh = (u16*)p;
    cudaGetSymbolAddress(&p, g_chbf_lo); chbl = (u16*)p;
    cudaGetSymbolAddress(&p, g_h676bf_hi); b676h = (u16*)p;
    cudaGetSymbolAddress(&p, g_h676bf_lo); b676l = (u16*)p;
    cudaGetSymbolAddress(&p, g_h1bf_hi); h1bh = (u16*)p;
    cudaGetSymbolAddress(&p, g_h1bf_lo); h1bl = (u16*)p;
    cudaGetSymbolAddress(&p, g_BPhh_hi); bphh_h = (u32*)p;
    cudaGetSymbolAddress(&p, g_BPhh_lo); bphh_l = (u32*)p;
    cudaGetSymbolAddress(&p, g_BPih_hi); bpih_h = (u32*)p;
    cudaGetSymbolAddress(&p, g_BPih_lo); bpih_l = (u32*)p;
    float* child[2] = { chA, chB };
    const float* whh = wcatT + 256*1024;
    const float* wih = wcatT;

    // prologue: 4 launches
    k_pre1<<<513, 256>>>(Wt, Wc, bc, bt);
    k_pre2<<<2332, 256>>>(W_ih, W_hh, b_ih, b_hh, emb, lstm_init);
    k_pre3<<<1055, 256>>>();
    k_leafxw<<<104, 256>>>(W_ih, b_ih, b_hh);

    const int leaf_off = 21845;   // (4^8-1)/3
    // 676 pair states (computes 26 states inline)
    gemm_small<3><<<dim3(43,8), 256>>>(nullptr, h676, nullptr, c676, whh,
                                       nullptr, leafxW, c1, 0, 676, b676h, b676l);
    // level 7
    {
        const int M = 16384;
        const int off7 = 5461;
        mma_step<4><<<dim3(M/64, 8), 256>>>(b676h, b676l, hA, bfAh, bfAl, c676, cbuf,
                                            bphh_h, bphh_l, idents + leaf_off, leafxW, c1, 0, M);
        mma_step<2><<<dim3(M/64, 8), 256>>>(bfAh, bfAl, hB, bfBh, bfBl, cbuf, cbuf,
                                            bphh_h, bphh_l, idents + leaf_off + 3, leafxW, c1, 0, M);
        tag_kernel<<<M/16, 256>>>(hB, idents + off7, child[0], M, chbh, chbl);
    }

    // levels 6..0
    int cur = 0;
    for (int l = 6; l >= 0; l--){
        int M = 1 << (2*l);
        int M4 = 4*M;
        int off = (M - 1)/3;
        // xw
        if (M4 >= 1024)
            mma_step<0><<<dim3(M4/64, 8), 256>>>(chbh, chbl, xw, nullptr, nullptr,
                                                 nullptr, nullptr, bpih_h, bpih_l,
                                                 nullptr, bzT, c1, 0, M4);
        else
            gemm_small<0><<<dim3((M4+15)/16, 8), 256>>>(child[cur], xw, nullptr, nullptr,
                                                        wih, nullptr, bzT, c1, 0, M4,
                                                        nullptr, nullptr);
        // 4 recurrent steps
        for (int t = 0; t < 4; t++){
            float* hout   = (t & 1) ? hB : hA;
            u16* hbo_h    = (t & 1) ? bfBh : bfAh;
            u16* hbo_l    = (t & 1) ? bfBl : bfAl;
            const u16* hi_h = (t == 0) ? h1bh : ((t & 1) ? bfAh : bfBh);
            const u16* hi_l = (t == 0) ? h1bl : ((t & 1) ? bfAl : bfBl);
            const float* hin = (t == 0) ? h1 : ((t & 1) ? hA : hB);
            if (M >= 1024)
                mma_step<1><<<dim3(M/64, 8), 256>>>(hi_h, hi_l, hout, hbo_h, hbo_l,
                                                    cbuf, cbuf, bphh_h, bphh_l,
                                                    nullptr, xw + t*1024, c1, (t==0)?1:0, M);
            else
                gemm_small<1><<<dim3((M+15)/16, 8), 256>>>(hin, hout, cbuf, cbuf, whh,
                                                           nullptr, xw + t*1024, c1,
                                                           (t==0)?1:0, M, nullptr, nullptr);
        }
        float* o = (l == 0) ? out : child[cur ^ 1];
        bool wantbf = (M >= 1024);
        tag_kernel<<<(M + 15)/16, 256>>>(hB, idents + off, o, M,
                                         wantbf ? chbh : nullptr, wantbf ? chbl : nullptr);
        cur ^= 1;
    }
}